// round 15
// baseline (speedup 1.0000x reference)
#include <cuda_runtime.h>
#include <math.h>

#define N_TOK   4096
#define DMODEL  256
#define NHEAD   4
#define DPH     64
#define NEXP    9
#define LN_EPS  1e-5f
#define ATT_SCALE 0.25f   // (dph // num_heads) ** -0.5 = 16^-0.5

typedef unsigned long long ull;
typedef unsigned int uint;

// -------- device scratch (sorted-domain layout) --------
__device__ float g_q[N_TOK * DMODEL];
__device__ float g_k[N_TOK * DMODEL];
__device__ float g_v[N_TOK * DMODEL];
__device__ float g_ctx[N_TOK * DMODEL];
__device__ int   g_perm[N_TOK];       // sorted pos -> original token
__device__ int   g_offsets[NEXP + 1];

// -------- tf32 mma helpers --------
__device__ __forceinline__ uint cvt_tf32(float x) {
    uint u; asm("cvt.rna.tf32.f32 %0, %1;" : "=r"(u) : "f"(x)); return u;
}
__device__ __forceinline__ void mma_tf32(float* d, const uint* a, uint b0, uint b1) {
    asm("mma.sync.aligned.m16n8k8.row.col.f32.tf32.tf32.f32 "
        "{%0,%1,%2,%3}, {%4,%5,%6,%7}, {%8,%9}, {%0,%1,%2,%3};"
        : "+f"(d[0]), "+f"(d[1]), "+f"(d[2]), "+f"(d[3])
        : "r"(a[0]), "r"(a[1]), "r"(a[2]), "r"(a[3]), "r"(b0), "r"(b1));
}

#define AP 20    // qkv As pitch (uints)
#define AP2 36   // proj_ln As pitch (uints)
#define BP 132   // qkv Bs pitch (uints)
#define BPP 264  // proj_ln Bs pitch (uints)
#define HP 264   // proj_ln h-buffer pitch (floats)
#define TP 68    // attn tile pitch

// -------- fused counting sort (1 block) --------
__global__ void k_sort(const int* __restrict__ label) {
    __shared__ int hist[NEXP], base[NEXP + 1], cur[NEXP];
    int t = threadIdx.x;
    if (t < NEXP) { hist[t] = 0; cur[t] = 0; }
    __syncthreads();
    for (int i = t; i < N_TOK; i += 1024) atomicAdd(&hist[label[i]], 1);
    __syncthreads();
    if (t == 0) {
        int off = 0;
        for (int e = 0; e < NEXP; e++) { base[e] = off; g_offsets[e] = off; off += hist[e]; }
        base[NEXP] = off; g_offsets[NEXP] = off;
    }
    __syncthreads();
    for (int i = t; i < N_TOK; i += 1024) {
        int l = label[i];
        int p = atomicAdd(&cur[l], 1);
        g_perm[base[l] + p] = i;
    }
}

// -------- fused grouped QKV GEMM: 64x128 tiles (R12/R13 version, reverted) --------
__global__ __launch_bounds__(256) void k_qkv(
    const float* __restrict__ x,
    const float* __restrict__ Wq, const float* __restrict__ bq,
    const float* __restrict__ Wk, const float* __restrict__ bk,
    const float* __restrict__ Wv, const float* __restrict__ bv)
{
    int g = blockIdx.z;
    int goff = g_offsets[g];
    int gcnt = g_offsets[g + 1] - goff;
    int row0 = blockIdx.x * 64;
    if (row0 >= gcnt) return;
    int rows = min(64, gcnt - row0);
    int col0 = blockIdx.y * 128;

    __shared__ __align__(16) uint As[64 * AP];
    __shared__ __align__(16) uint Bs[3][16 * BP];
    __shared__ int Ts[64];

    int tid = threadIdx.x;
    if (tid < 64) Ts[tid] = g_perm[goff + row0 + min(tid, rows - 1)];
    __syncthreads();

    int lane = tid & 31, warp = tid >> 5;
    int wm = warp & 1, wn = warp >> 1;
    int gq = lane >> 2, tg = lane & 3;

    float acc[3][2][4][4];
#pragma unroll
    for (int m = 0; m < 3; m++)
#pragma unroll
        for (int i = 0; i < 2; i++)
#pragma unroll
            for (int j = 0; j < 4; j++)
#pragma unroll
                for (int e = 0; e < 4; e++) acc[m][i][j][e] = 0.f;

    int am = tid & 63, aseg = tid >> 6;
    int bkk = tid >> 4, bn = (tid & 15) * 8;
    const float* Aptr = x + (size_t)Ts[am] * DMODEL + aseg * 4;
    size_t woff = (size_t)g * DMODEL * DMODEL + (size_t)bkk * DMODEL + col0 + bn;
    const float* Bq = Wq + woff;
    const float* Bk = Wk + woff;
    const float* Bv = Wv + woff;

    float4 av = *(const float4*)(Aptr);
    float4 q0 = *(const float4*)(Bq), q1 = *(const float4*)(Bq + 4);
    float4 k0 = *(const float4*)(Bk), k1 = *(const float4*)(Bk + 4);
    float4 v0 = *(const float4*)(Bv), v1 = *(const float4*)(Bv + 4);

    for (int kk0 = 0; kk0 < DMODEL; kk0 += 16) {
        __syncthreads();
        {
            uint4 ua = {cvt_tf32(av.x), cvt_tf32(av.y), cvt_tf32(av.z), cvt_tf32(av.w)};
            *(uint4*)&As[am * AP + aseg * 4] = ua;
            uint4 w;
            w.x = cvt_tf32(q0.x); w.y = cvt_tf32(q0.y); w.z = cvt_tf32(q0.z); w.w = cvt_tf32(q0.w);
            *(uint4*)&Bs[0][bkk * BP + bn] = w;
            w.x = cvt_tf32(q1.x); w.y = cvt_tf32(q1.y); w.z = cvt_tf32(q1.z); w.w = cvt_tf32(q1.w);
            *(uint4*)&Bs[0][bkk * BP + bn + 4] = w;
            w.x = cvt_tf32(k0.x); w.y = cvt_tf32(k0.y); w.z = cvt_tf32(k0.z); w.w = cvt_tf32(k0.w);
            *(uint4*)&Bs[1][bkk * BP + bn] = w;
            w.x = cvt_tf32(k1.x); w.y = cvt_tf32(k1.y); w.z = cvt_tf32(k1.z); w.w = cvt_tf32(k1.w);
            *(uint4*)&Bs[1][bkk * BP + bn + 4] = w;
            w.x = cvt_tf32(v0.x); w.y = cvt_tf32(v0.y); w.z = cvt_tf32(v0.z); w.w = cvt_tf32(v0.w);
            *(uint4*)&Bs[2][bkk * BP + bn] = w;
            w.x = cvt_tf32(v1.x); w.y = cvt_tf32(v1.y); w.z = cvt_tf32(v1.z); w.w = cvt_tf32(v1.w);
            *(uint4*)&Bs[2][bkk * BP + bn + 4] = w;
        }
        __syncthreads();
        if (kk0 + 16 < DMODEL) {
            av = *(const float4*)(Aptr + kk0 + 16);
            size_t o = (size_t)(kk0 + 16) * DMODEL;
            q0 = *(const float4*)(Bq + o); q1 = *(const float4*)(Bq + o + 4);
            k0 = *(const float4*)(Bk + o); k1 = *(const float4*)(Bk + o + 4);
            v0 = *(const float4*)(Bv + o); v1 = *(const float4*)(Bv + o + 4);
        }
#pragma unroll
        for (int ka = 0; ka < 2; ka++) {
            int kb = ka * 8;
            uint af[2][4];
#pragma unroll
            for (int i = 0; i < 2; i++) {
                int r0 = wm * 32 + i * 16;
                af[i][0] = As[(r0 + gq)     * AP + kb + tg];
                af[i][1] = As[(r0 + gq + 8) * AP + kb + tg];
                af[i][2] = As[(r0 + gq)     * AP + kb + tg + 4];
                af[i][3] = As[(r0 + gq + 8) * AP + kb + tg + 4];
            }
#pragma unroll
            for (int m = 0; m < 3; m++) {
#pragma unroll
                for (int j = 0; j < 4; j++) {
                    int nc = wn * 32 + j * 8 + gq;
                    uint b0 = Bs[m][(kb + tg)     * BP + nc];
                    uint b1 = Bs[m][(kb + tg + 4) * BP + nc];
                    mma_tf32(acc[m][0][j], af[0], b0, b1);
                    mma_tf32(acc[m][1][j], af[1], b0, b1);
                }
            }
        }
    }

#pragma unroll
    for (int m = 0; m < 3; m++) {
        const float* bias = (m == 0) ? bq : (m == 1) ? bk : bv;
        float* dst = (m == 0) ? g_q : (m == 1) ? g_k : g_v;
        bias += g * DMODEL;
#pragma unroll
        for (int i = 0; i < 2; i++) {
            int rbase = wm * 32 + i * 16 + gq;
#pragma unroll
            for (int j = 0; j < 4; j++) {
                int col = col0 + wn * 32 + j * 8 + tg * 2;
                float2 b2 = *(const float2*)&bias[col];
                if (rbase < rows) {
                    float2 o = {acc[m][i][j][0] + b2.x, acc[m][i][j][1] + b2.y};
                    *(float2*)&dst[(size_t)(goff + row0 + rbase) * DMODEL + col] = o;
                }
                if (rbase + 8 < rows) {
                    float2 o = {acc[m][i][j][2] + b2.x, acc[m][i][j][3] + b2.y};
                    *(float2*)&dst[(size_t)(goff + row0 + rbase + 8) * DMODEL + col] = o;
                }
            }
        }
    }
}

// -------- per-group flash attention: 128-q tiles, Q in registers (no reg cap) --------
// grid (32, 9, 4), block 256. Warp w owns q-rows [16w, 16w+16), full 64-k range.
// dyn smem: (Ks 2*64 + Vt 2*64 + Ps 128) * TP * 4 = 104448 B.
__global__ __launch_bounds__(256) void k_attn()
{
    int g = blockIdx.y, h = blockIdx.z;
    int goff = g_offsets[g];
    int gcnt = g_offsets[g + 1] - goff;
    int row0 = blockIdx.x * 128;
    if (row0 >= gcnt) return;
    int rows = min(128, gcnt - row0);

    extern __shared__ __align__(16) uint smu[];
    uint* Ks0 = smu;                      // [kj][d] x2 buffers (64 rows each)
    uint* Vt0 = Ks0 + 2 * 64 * TP;        // [d][kj] x2 buffers
    uint* Ps = Vt0 + 2 * 64 * TP;         // [qi][kj] 128 rows, warp-private

    int tid = threadIdx.x;
    int lane = tid & 31, warp = tid >> 5;  // 0..7
    int gq = lane >> 2, tg = lane & 3;
    int li = tid & 63, seg = tid >> 6, d0 = seg * 16;   // K/V loader: 16 d of row li

    int qrow_a = warp * 16 + gq;

    // ---- Q fragments in registers (loop-invariant; scale folded in) ----
    uint qf[8][4];
    {
        int ra = goff + row0 + min(qrow_a, rows - 1);
        int rb = goff + row0 + min(qrow_a + 8, rows - 1);
        const float* qa = g_q + (size_t)ra * DMODEL + h * DPH;
        const float* qb = g_q + (size_t)rb * DMODEL + h * DPH;
#pragma unroll
        for (int kb8 = 0; kb8 < 8; kb8++) {
            int c = kb8 * 8 + tg;
            qf[kb8][0] = cvt_tf32(qa[c] * ATT_SCALE);
            qf[kb8][1] = cvt_tf32(qb[c] * ATT_SCALE);
            qf[kb8][2] = cvt_tf32(qa[c + 4] * ATT_SCALE);
            qf[kb8][3] = cvt_tf32(qb[c + 4] * ATT_SCALE);
        }
    }

    // stage K/V tile 0 -> buffer 0
    {
        int kcnt0 = min(64, gcnt);
        int krow = goff + min(li, kcnt0 - 1);
        const float* kptr = g_k + (size_t)krow * DMODEL + h * DPH + d0;
        const float* vptr = g_v + (size_t)krow * DMODEL + h * DPH + d0;
#pragma unroll
        for (int f = 0; f < 4; f++) {
            float4 kv = *(const float4*)(kptr + 4 * f);
            uint4 uk = {cvt_tf32(kv.x), cvt_tf32(kv.y), cvt_tf32(kv.z), cvt_tf32(kv.w)};
            *(uint4*)&Ks0[li * TP + d0 + 4 * f] = uk;
            float4 vv = *(const float4*)(vptr + 4 * f);
            Vt0[(d0 + 4 * f + 0) * TP + li] = cvt_tf32(vv.x);
            Vt0[(d0 + 4 * f + 1) * TP + li] = cvt_tf32(vv.y);
            Vt0[(d0 + 4 * f + 2) * TP + li] = cvt_tf32(vv.z);
            Vt0[(d0 + 4 * f + 3) * TP + li] = cvt_tf32(vv.w);
        }
    }

    float O[8][4];
#pragma unroll
    for (int j = 0; j < 8; j++)
#pragma unroll
        for (int e = 0; e < 4; e++) O[j][e] = 0.f;
    float lsum0 = 0.f, lsum1 = 0.f;

    int buf = 0;

    for (int kc0 = 0; kc0 < gcnt; kc0 += 64) {
        int kcnt = min(64, gcnt - kc0);
        __syncthreads();              // staging(t) visible; prior tile consumed
        uint* Ks = Ks0 + buf * 64 * TP;
        uint* Vt = Vt0 + buf * 64 * TP;

        // ---- S = Q K^T : warp tile 16q x 64k (Q from registers) ----
        float S[8][4];
#pragma unroll
        for (int j = 0; j < 8; j++)
#pragma unroll
            for (int e = 0; e < 4; e++) S[j][e] = 0.f;
#pragma unroll
        for (int kb8 = 0; kb8 < 8; kb8++) {
            int kb = kb8 * 8;
#pragma unroll
            for (int j = 0; j < 8; j++) {
                int nc = j * 8 + gq;
                uint b0 = Ks[nc * TP + kb + tg];
                uint b1 = Ks[nc * TP + kb + tg + 4];
                mma_tf32(S[j], qf[kb8], b0, b1);
            }
        }

        // ---- exp (no-max; scores bounded) + mask + warp-private Ps + lsum ----
#pragma unroll
        for (int j = 0; j < 8; j++) {
            int c0 = j * 8 + 2 * tg;
            bool v0 = c0 < kcnt, v1 = c0 + 1 < kcnt;
            float p00 = v0 ? __expf(S[j][0]) : 0.f;
            float p01 = v1 ? __expf(S[j][1]) : 0.f;
            float p10 = v0 ? __expf(S[j][2]) : 0.f;
            float p11 = v1 ? __expf(S[j][3]) : 0.f;
            lsum0 += p00 + p01;
            lsum1 += p10 + p11;
            uint2 ua = {cvt_tf32(p00), cvt_tf32(p01)};
            *(uint2*)&Ps[qrow_a * TP + c0] = ua;
            uint2 ub = {cvt_tf32(p10), cvt_tf32(p11)};
            *(uint2*)&Ps[(qrow_a + 8) * TP + c0] = ub;
        }

        // ---- stage next tile into other buffer (latency hides under PV) ----
        if (kc0 + 64 < gcnt) {
            uint* Kn = Ks0 + (buf ^ 1) * 64 * TP;
            uint* Vn = Vt0 + (buf ^ 1) * 64 * TP;
            int kcn = min(64, gcnt - kc0 - 64);
            int krow = goff + kc0 + 64 + min(li, kcn - 1);
            const float* kptr = g_k + (size_t)krow * DMODEL + h * DPH + d0;
            const float* vptr = g_v + (size_t)krow * DMODEL + h * DPH + d0;
#pragma unroll
            for (int f = 0; f < 4; f++) {
                float4 kv = *(const float4*)(kptr + 4 * f);
                uint4 uk = {cvt_tf32(kv.x), cvt_tf32(kv.y), cvt_tf32(kv.z), cvt_tf32(kv.w)};
                *(uint4*)&Kn[li * TP + d0 + 4 * f] = uk;
                float4 vv = *(const float4*)(vptr + 4 * f);
                Vn[(d0 + 4 * f + 0) * TP + li] = cvt_tf32(vv.x);
                Vn[(d0 + 4 * f + 1) * TP + li] = cvt_tf32(vv.y);
                Vn[(d0 + 4 * f + 2) * TP + li] = cvt_tf32(vv.z);
                Vn[(d0 + 4 * f + 3) * TP + li] = cvt_tf32(vv.w);
            }
        }
        __syncwarp();   // order Ps stores before warp-local PV reads

        // ---- O += P V : warp tile 16q x 64d ----
#pragma unroll
        for (int kb = 0; kb < 64; kb += 8) {
            uint af[4];
            af[0] = Ps[qrow_a * TP + kb + tg];
            af[1] = Ps[(qrow_a + 8) * TP + kb + tg];
            af[2] = Ps[qrow_a * TP + kb + tg + 4];
            af[3] = Ps[(qrow_a + 8) * TP + kb + tg + 4];
#pragma unroll
            for (int j = 0; j < 8; j++) {
                int nc = j * 8 + gq;
                uint b0 = Vt[nc * TP + kb + tg];
                uint b1 = Vt[nc * TP + kb + tg + 4];
                mma_tf32(O[j], af, b0, b1);
            }
        }
        buf ^= 1;
    }

    lsum0 += __shfl_xor_sync(0xffffffffu, lsum0, 1);
    lsum0 += __shfl_xor_sync(0xffffffffu, lsum0, 2);
    lsum1 += __shfl_xor_sync(0xffffffffu, lsum1, 1);
    lsum1 += __shfl_xor_sync(0xffffffffu, lsum1, 2);
    float inv0 = 1.f / lsum0;
    float inv1 = 1.f / lsum1;

#pragma unroll
    for (int j = 0; j < 8; j++) {
        int col = h * DPH + j * 8 + 2 * tg;
        if (qrow_a < rows) {
            float2 o = {O[j][0] * inv0, O[j][1] * inv0};
            *(float2*)&g_ctx[(size_t)(goff + row0 + qrow_a) * DMODEL + col] = o;
        }
        if (qrow_a + 8 < rows) {
            float2 o = {O[j][2] * inv1, O[j][3] * inv1};
            *(float2*)&g_ctx[(size_t)(goff + row0 + qrow_a + 8) * DMODEL + col] = o;
        }
    }
}

// -------- fused output projection + residual + LayerNorm: 16-row tiles (R13, unchanged) --------
__global__ __launch_bounds__(256) void k_proj_ln(
    const float* __restrict__ x,
    const float* __restrict__ Wf, const float* __restrict__ bf,
    const float* __restrict__ gamma, const float* __restrict__ beta,
    float* __restrict__ out)
{
    int row0 = blockIdx.x * 16;

    extern __shared__ __align__(16) uint dsm[];
    uint* As0 = dsm;
    uint* Bs0 = dsm + 2 * 16 * AP2;
    __shared__ int Ts[16];

    int tid = threadIdx.x;
    if (tid < 16) Ts[tid] = g_perm[row0 + tid];
    __syncthreads();

    int lane = tid & 31, warp = tid >> 5;
    int gq = lane >> 2, tg = lane & 3;

    float acc[4][4];
#pragma unroll
    for (int j = 0; j < 4; j++)
#pragma unroll
        for (int e = 0; e < 4; e++) acc[j][e] = 0.f;

    int am = tid & 15, aseg = (tid >> 4) & 7;
    int bkk = tid >> 5, bn = (tid & 31) * 8;
    const float* Aptr = g_ctx + (size_t)(row0 + am) * DMODEL + aseg * 4;
    const float* Bptr = Wf + (size_t)bkk * DMODEL + bn;

    float4 av, bv[8];
#define PLN_LOAD(s)                                                        \
    {   int kk0 = (s) * 32;                                                \
        if (tid < 128) av = *(const float4*)(Aptr + kk0);                  \
        _Pragma("unroll")                                                  \
        for (int t = 0; t < 4; t++) {                                      \
            bv[2 * t]     = *(const float4*)(Bptr + (size_t)(kk0 + 8 * t) * DMODEL);     \
            bv[2 * t + 1] = *(const float4*)(Bptr + (size_t)(kk0 + 8 * t) * DMODEL + 4); \
        } }
#define PLN_STORE(b_)                                                      \
    {   if (tid < 128) {                                                   \
            uint4 ua = {cvt_tf32(av.x), cvt_tf32(av.y), cvt_tf32(av.z), cvt_tf32(av.w)}; \
            *(uint4*)&As0[(b_) * 16 * AP2 + am * AP2 + aseg * 4] = ua;     \
        }                                                                  \
        _Pragma("unroll")                                                  \
        for (int t = 0; t < 4; t++) {                                      \
            uint4 w0 = {cvt_tf32(bv[2*t].x), cvt_tf32(bv[2*t].y), cvt_tf32(bv[2*t].z), cvt_tf32(bv[2*t].w)}; \
            uint4 w1 = {cvt_tf32(bv[2*t+1].x), cvt_tf32(bv[2*t+1].y), cvt_tf32(bv[2*t+1].z), cvt_tf32(bv[2*t+1].w)}; \
            *(uint4*)&Bs0[(b_) * 32 * BPP + (bkk + 8 * t) * BPP + bn]     = w0; \
            *(uint4*)&Bs0[(b_) * 32 * BPP + (bkk + 8 * t) * BPP + bn + 4] = w1; \
        } }

    PLN_LOAD(0);
    PLN_STORE(0);
    __syncthreads();
#pragma unroll
    for (int s = 0; s < 8; s++) {
        int cur = s & 1;
        if (s < 7) PLN_LOAD(s + 1);
        const uint* As = As0 + cur * 16 * AP2;
        const uint* Bs = Bs0 + cur * 32 * BPP;
#pragma unroll
        for (int kb = 0; kb < 32; kb += 8) {
            uint af[4];
            af[0] = As[gq       * AP2 + kb + tg];
            af[1] = As[(gq + 8) * AP2 + kb + tg];
            af[2] = As[gq       * AP2 + kb + tg + 4];
            af[3] = As[(gq + 8) * AP2 + kb + tg + 4];
#pragma unroll
            for (int j = 0; j < 4; j++) {
                int nc = warp * 32 + j * 8 + gq;
                uint b0 = Bs[(kb + tg)     * BPP + nc];
                uint b1 = Bs[(kb + tg + 4) * BPP + nc];
                mma_tf32(acc[j], af, b0, b1);
            }
        }
        if (s < 7) {
            PLN_STORE(cur ^ 1);
            __syncthreads();
        }
    }

    __syncthreads();
    float* Hs = (float*)dsm;
#pragma unroll
    for (int j = 0; j < 4; j++) {
        int col = warp * 32 + j * 8 + tg * 2;
        float2 b2 = *(const float2*)&bf[col];
        float2 xa = *(const float2*)&x[(size_t)Ts[gq] * DMODEL + col];
        float2 xb = *(const float2*)&x[(size_t)Ts[gq + 8] * DMODEL + col];
        Hs[gq * HP + col]     = acc[j][0] + b2.x + xa.x;
        Hs[gq * HP + col + 1] = acc[j][1] + b2.y + xa.y;
        Hs[(gq + 8) * HP + col]     = acc[j][2] + b2.x + xb.x;
        Hs[(gq + 8) * HP + col + 1] = acc[j][3] + b2.y + xb.y;
    }
    __syncthreads();

#pragma unroll
    for (int i = 0; i < 2; i++) {
        int row = warp * 2 + i;
        float4 v0 = *(const float4*)&Hs[row * HP + lane * 8];
        float4 v1 = *(const float4*)&Hs[row * HP + lane * 8 + 4];
        float s  = (v0.x + v0.y + v0.z + v0.w) + (v1.x + v1.y + v1.z + v1.w);
        float sq = v0.x * v0.x + v0.y * v0.y + v0.z * v0.z + v0.w * v0.w
                 + v1.x * v1.x + v1.y * v1.y + v1.z * v1.z + v1.w * v1.w;
#pragma unroll
        for (int off = 16; off > 0; off >>= 1) {
            s  += __shfl_xor_sync(0xffffffffu, s, off);
            sq += __shfl_xor_sync(0xffffffffu, sq, off);
        }
        float mean = s * (1.f / DMODEL);
        float var  = sq * (1.f / DMODEL) - mean * mean;
        float inv  = rsqrtf(var + LN_EPS);
        int orow = Ts[row];
        float4 g0 = *(const float4*)&gamma[lane * 8];
        float4 g1 = *(const float4*)&gamma[lane * 8 + 4];
        float4 be0 = *(const float4*)&beta[lane * 8];
        float4 be1 = *(const float4*)&beta[lane * 8 + 4];
        float4 o0 = {g0.x * (v0.x - mean) * inv + be0.x,
                     g0.y * (v0.y - mean) * inv + be0.y,
                     g0.z * (v0.z - mean) * inv + be0.z,
                     g0.w * (v0.w - mean) * inv + be0.w};
        float4 o1 = {g1.x * (v1.x - mean) * inv + be1.x,
                     g1.y * (v1.y - mean) * inv + be1.y,
                     g1.z * (v1.z - mean) * inv + be1.z,
                     g1.w * (v1.w - mean) * inv + be1.w};
        *(float4*)&out[(size_t)orow * DMODEL + lane * 8]     = o0;
        *(float4*)&out[(size_t)orow * DMODEL + lane * 8 + 4] = o1;
    }
}

// -------- launch --------
extern "C" void kernel_launch(void* const* d_in, const int* in_sizes, int n_in,
                              void* d_out, int out_size)
{
    const float* x     = (const float*)d_in[0];
    const int*   label = (const int*)  d_in[1];
    const float* Wq    = (const float*)d_in[2];
    const float* bq    = (const float*)d_in[3];
    const float* Wk    = (const float*)d_in[4];
    const float* bk    = (const float*)d_in[5];
    const float* Wv    = (const float*)d_in[6];
    const float* bv    = (const float*)d_in[7];
    const float* Wf    = (const float*)d_in[8];
    const float* bf    = (const float*)d_in[9];
    const float* gamma = (const float*)d_in[10];
    const float* beta  = (const float*)d_in[11];
    float* out = (float*)d_out;

    const int ATTN_SMEM = (2 * 64 + 2 * 64 + 128) * TP * 4;   // 104448 B
    const int PLN_SMEM  = (2 * 16 * AP2 + 2 * 32 * BPP) * 4;  // 72192 B

    static bool attr_done = false;
    if (!attr_done) {
        cudaFuncSetAttribute(k_attn, cudaFuncAttributeMaxDynamicSharedMemorySize, ATTN_SMEM);
        cudaFuncSetAttribute(k_attn, cudaFuncAttributePreferredSharedMemoryCarveout, 100);
        cudaFuncSetAttribute(k_proj_ln, cudaFuncAttributeMaxDynamicSharedMemorySize, PLN_SMEM);
        cudaFuncSetAttribute(k_proj_ln, cudaFuncAttributePreferredSharedMemoryCarveout, 100);
        attr_done = true;
    }

    k_sort<<<1, 1024>>>(label);
    k_qkv<<<dim3(64, 2, NEXP), 256>>>(x, Wq, bq, Wk, bk, Wv, bv);
    k_attn<<<dim3(32, NEXP, NHEAD), 256, ATTN_SMEM>>>();
    k_proj_ln<<<256, 256, PLN_SMEM>>>(x, Wf, bf, gamma, beta, out);
}

// round 16
// speedup vs baseline: 1.2004x; 1.2004x over previous
#include <cuda_runtime.h>
#include <math.h>

#define N_TOK   4096
#define DMODEL  256
#define NHEAD   4
#define DPH     64
#define NEXP    9
#define LN_EPS  1e-5f
#define ATT_SCALE 0.25f   // (dph // num_heads) ** -0.5 = 16^-0.5

typedef unsigned long long ull;
typedef unsigned int uint;

// -------- device scratch (sorted-domain layout) --------
__device__ float g_q[N_TOK * DMODEL];
__device__ float g_k[N_TOK * DMODEL];
__device__ float g_v[N_TOK * DMODEL];
__device__ float g_ctx[N_TOK * DMODEL];
__device__ int   g_perm[N_TOK];       // sorted pos -> original token
__device__ int   g_offsets[NEXP + 1];

// -------- tf32 mma helpers --------
__device__ __forceinline__ uint cvt_tf32(float x) {
    uint u; asm("cvt.rna.tf32.f32 %0, %1;" : "=r"(u) : "f"(x)); return u;
}
__device__ __forceinline__ void mma_tf32(float* d, const uint* a, uint b0, uint b1) {
    asm("mma.sync.aligned.m16n8k8.row.col.f32.tf32.tf32.f32 "
        "{%0,%1,%2,%3}, {%4,%5,%6,%7}, {%8,%9}, {%0,%1,%2,%3};"
        : "+f"(d[0]), "+f"(d[1]), "+f"(d[2]), "+f"(d[3])
        : "r"(a[0]), "r"(a[1]), "r"(a[2]), "r"(a[3]), "r"(b0), "r"(b1));
}

#define AP 20    // qkv As pitch (uints)
#define AP2 36   // proj_ln As pitch (uints)
#define BP 132   // qkv Bs pitch (uints)
#define BPP 264  // proj_ln Bs pitch (uints)
#define HP 264   // proj_ln h-buffer pitch (floats)
#define TP 68    // attn tile pitch

// -------- fused counting sort (1 block) --------
__global__ void k_sort(const int* __restrict__ label) {
    __shared__ int hist[NEXP], base[NEXP + 1], cur[NEXP];
    int t = threadIdx.x;
    if (t < NEXP) { hist[t] = 0; cur[t] = 0; }
    __syncthreads();
    for (int i = t; i < N_TOK; i += 1024) atomicAdd(&hist[label[i]], 1);
    __syncthreads();
    if (t == 0) {
        int off = 0;
        for (int e = 0; e < NEXP; e++) { base[e] = off; g_offsets[e] = off; off += hist[e]; }
        base[NEXP] = off; g_offsets[NEXP] = off;
    }
    __syncthreads();
    for (int i = t; i < N_TOK; i += 1024) {
        int l = label[i];
        int p = atomicAdd(&cur[l], 1);
        g_perm[base[l] + p] = i;
    }
}

// -------- fused grouped QKV GEMM: 64x128 tiles (R12/R13 version) --------
__global__ __launch_bounds__(256) void k_qkv(
    const float* __restrict__ x,
    const float* __restrict__ Wq, const float* __restrict__ bq,
    const float* __restrict__ Wk, const float* __restrict__ bk,
    const float* __restrict__ Wv, const float* __restrict__ bv)
{
    int g = blockIdx.z;
    int goff = g_offsets[g];
    int gcnt = g_offsets[g + 1] - goff;
    int row0 = blockIdx.x * 64;
    if (row0 >= gcnt) return;
    int rows = min(64, gcnt - row0);
    int col0 = blockIdx.y * 128;

    __shared__ __align__(16) uint As[64 * AP];
    __shared__ __align__(16) uint Bs[3][16 * BP];
    __shared__ int Ts[64];

    int tid = threadIdx.x;
    if (tid < 64) Ts[tid] = g_perm[goff + row0 + min(tid, rows - 1)];
    __syncthreads();

    int lane = tid & 31, warp = tid >> 5;
    int wm = warp & 1, wn = warp >> 1;
    int gq = lane >> 2, tg = lane & 3;

    float acc[3][2][4][4];
#pragma unroll
    for (int m = 0; m < 3; m++)
#pragma unroll
        for (int i = 0; i < 2; i++)
#pragma unroll
            for (int j = 0; j < 4; j++)
#pragma unroll
                for (int e = 0; e < 4; e++) acc[m][i][j][e] = 0.f;

    int am = tid & 63, aseg = tid >> 6;
    int bkk = tid >> 4, bn = (tid & 15) * 8;
    const float* Aptr = x + (size_t)Ts[am] * DMODEL + aseg * 4;
    size_t woff = (size_t)g * DMODEL * DMODEL + (size_t)bkk * DMODEL + col0 + bn;
    const float* Bq = Wq + woff;
    const float* Bk = Wk + woff;
    const float* Bv = Wv + woff;

    float4 av = *(const float4*)(Aptr);
    float4 q0 = *(const float4*)(Bq), q1 = *(const float4*)(Bq + 4);
    float4 k0 = *(const float4*)(Bk), k1 = *(const float4*)(Bk + 4);
    float4 v0 = *(const float4*)(Bv), v1 = *(const float4*)(Bv + 4);

    for (int kk0 = 0; kk0 < DMODEL; kk0 += 16) {
        __syncthreads();
        {
            uint4 ua = {cvt_tf32(av.x), cvt_tf32(av.y), cvt_tf32(av.z), cvt_tf32(av.w)};
            *(uint4*)&As[am * AP + aseg * 4] = ua;
            uint4 w;
            w.x = cvt_tf32(q0.x); w.y = cvt_tf32(q0.y); w.z = cvt_tf32(q0.z); w.w = cvt_tf32(q0.w);
            *(uint4*)&Bs[0][bkk * BP + bn] = w;
            w.x = cvt_tf32(q1.x); w.y = cvt_tf32(q1.y); w.z = cvt_tf32(q1.z); w.w = cvt_tf32(q1.w);
            *(uint4*)&Bs[0][bkk * BP + bn + 4] = w;
            w.x = cvt_tf32(k0.x); w.y = cvt_tf32(k0.y); w.z = cvt_tf32(k0.z); w.w = cvt_tf32(k0.w);
            *(uint4*)&Bs[1][bkk * BP + bn] = w;
            w.x = cvt_tf32(k1.x); w.y = cvt_tf32(k1.y); w.z = cvt_tf32(k1.z); w.w = cvt_tf32(k1.w);
            *(uint4*)&Bs[1][bkk * BP + bn + 4] = w;
            w.x = cvt_tf32(v0.x); w.y = cvt_tf32(v0.y); w.z = cvt_tf32(v0.z); w.w = cvt_tf32(v0.w);
            *(uint4*)&Bs[2][bkk * BP + bn] = w;
            w.x = cvt_tf32(v1.x); w.y = cvt_tf32(v1.y); w.z = cvt_tf32(v1.z); w.w = cvt_tf32(v1.w);
            *(uint4*)&Bs[2][bkk * BP + bn + 4] = w;
        }
        __syncthreads();
        if (kk0 + 16 < DMODEL) {
            av = *(const float4*)(Aptr + kk0 + 16);
            size_t o = (size_t)(kk0 + 16) * DMODEL;
            q0 = *(const float4*)(Bq + o); q1 = *(const float4*)(Bq + o + 4);
            k0 = *(const float4*)(Bk + o); k1 = *(const float4*)(Bk + o + 4);
            v0 = *(const float4*)(Bv + o); v1 = *(const float4*)(Bv + o + 4);
        }
#pragma unroll
        for (int ka = 0; ka < 2; ka++) {
            int kb = ka * 8;
            uint af[2][4];
#pragma unroll
            for (int i = 0; i < 2; i++) {
                int r0 = wm * 32 + i * 16;
                af[i][0] = As[(r0 + gq)     * AP + kb + tg];
                af[i][1] = As[(r0 + gq + 8) * AP + kb + tg];
                af[i][2] = As[(r0 + gq)     * AP + kb + tg + 4];
                af[i][3] = As[(r0 + gq + 8) * AP + kb + tg + 4];
            }
#pragma unroll
            for (int m = 0; m < 3; m++) {
#pragma unroll
                for (int j = 0; j < 4; j++) {
                    int nc = wn * 32 + j * 8 + gq;
                    uint b0 = Bs[m][(kb + tg)     * BP + nc];
                    uint b1 = Bs[m][(kb + tg + 4) * BP + nc];
                    mma_tf32(acc[m][0][j], af[0], b0, b1);
                    mma_tf32(acc[m][1][j], af[1], b0, b1);
                }
            }
        }
    }

#pragma unroll
    for (int m = 0; m < 3; m++) {
        const float* bias = (m == 0) ? bq : (m == 1) ? bk : bv;
        float* dst = (m == 0) ? g_q : (m == 1) ? g_k : g_v;
        bias += g * DMODEL;
#pragma unroll
        for (int i = 0; i < 2; i++) {
            int rbase = wm * 32 + i * 16 + gq;
#pragma unroll
            for (int j = 0; j < 4; j++) {
                int col = col0 + wn * 32 + j * 8 + tg * 2;
                float2 b2 = *(const float2*)&bias[col];
                if (rbase < rows) {
                    float2 o = {acc[m][i][j][0] + b2.x, acc[m][i][j][1] + b2.y};
                    *(float2*)&dst[(size_t)(goff + row0 + rbase) * DMODEL + col] = o;
                }
                if (rbase + 8 < rows) {
                    float2 o = {acc[m][i][j][2] + b2.x, acc[m][i][j][3] + b2.y};
                    *(float2*)&dst[(size_t)(goff + row0 + rbase + 8) * DMODEL + col] = o;
                }
            }
        }
    }
}

// -------- per-group flash attention: 128-q tiles, Qs in smem (R13), early K/V prefetch --------
// grid (32, 9, 4), block 256. Warp w owns q-rows [16w, 16w+16), full 64-k range.
// dyn smem: (Qs 128 + Ks 2*64 + Vt 2*64 + Ps 128) * TP * 4 = 139264 B.
__global__ __launch_bounds__(256) void k_attn()
{
    int g = blockIdx.y, h = blockIdx.z;
    int goff = g_offsets[g];
    int gcnt = g_offsets[g + 1] - goff;
    int row0 = blockIdx.x * 128;
    if (row0 >= gcnt) return;
    int rows = min(128, gcnt - row0);

    extern __shared__ __align__(16) uint smu[];
    uint* Qs = smu;                       // [qi][d] 128 rows, pitch TP (pre-scaled)
    uint* Ks0 = Qs + 128 * TP;            // [kj][d] x2 buffers (64 rows each)
    uint* Vt0 = Ks0 + 2 * 64 * TP;        // [d][kj] x2 buffers
    uint* Ps = Vt0 + 2 * 64 * TP;         // [qi][kj] 128 rows, warp-private

    int tid = threadIdx.x;
    int lane = tid & 31, warp = tid >> 5;  // 0..7
    int gq = lane >> 2, tg = lane & 3;
    int li = tid & 63, seg = tid >> 6, d0 = seg * 16;       // K/V loader: 16 d of row li
    int qli = tid & 127, qseg = tid >> 7, d0q = qseg * 32;  // Q loader: 32 d of row qli

    // stage Q once (scaled, tf32)
    {
        const float* qptr = g_q + (size_t)(goff + row0 + min(qli, rows - 1)) * DMODEL + h * DPH + d0q;
#pragma unroll
        for (int f = 0; f < 8; f++) {
            float4 v = *(const float4*)(qptr + 4 * f);
            uint4 u = {cvt_tf32(v.x * ATT_SCALE), cvt_tf32(v.y * ATT_SCALE),
                       cvt_tf32(v.z * ATT_SCALE), cvt_tf32(v.w * ATT_SCALE)};
            *(uint4*)&Qs[qli * TP + d0q + 4 * f] = u;
        }
    }

    // stage K/V tile 0 -> buffer 0
    {
        int kcnt0 = min(64, gcnt);
        int krow = goff + min(li, kcnt0 - 1);
        const float* kptr = g_k + (size_t)krow * DMODEL + h * DPH + d0;
        const float* vptr = g_v + (size_t)krow * DMODEL + h * DPH + d0;
#pragma unroll
        for (int f = 0; f < 4; f++) {
            float4 kv = *(const float4*)(kptr + 4 * f);
            uint4 uk = {cvt_tf32(kv.x), cvt_tf32(kv.y), cvt_tf32(kv.z), cvt_tf32(kv.w)};
            *(uint4*)&Ks0[li * TP + d0 + 4 * f] = uk;
            float4 vv = *(const float4*)(vptr + 4 * f);
            Vt0[(d0 + 4 * f + 0) * TP + li] = cvt_tf32(vv.x);
            Vt0[(d0 + 4 * f + 1) * TP + li] = cvt_tf32(vv.y);
            Vt0[(d0 + 4 * f + 2) * TP + li] = cvt_tf32(vv.z);
            Vt0[(d0 + 4 * f + 3) * TP + li] = cvt_tf32(vv.w);
        }
    }

    float O[8][4];
#pragma unroll
    for (int j = 0; j < 8; j++)
#pragma unroll
        for (int e = 0; e < 4; e++) O[j][e] = 0.f;
    float lsum0 = 0.f, lsum1 = 0.f;

    int buf = 0;
    int qrow_a = warp * 16 + gq;

    for (int kc0 = 0; kc0 < gcnt; kc0 += 64) {
        int kcnt = min(64, gcnt - kc0);
        __syncthreads();              // staging(t) visible; prior tile consumed
        uint* Ks = Ks0 + buf * 64 * TP;
        uint* Vt = Vt0 + buf * 64 * TP;

        // ---- S = Q K^T : warp tile 16q x 64k ----
        float S[8][4];
#pragma unroll
        for (int j = 0; j < 8; j++)
#pragma unroll
            for (int e = 0; e < 4; e++) S[j][e] = 0.f;
#pragma unroll
        for (int kb = 0; kb < 64; kb += 8) {
            uint af[4];
            af[0] = Qs[qrow_a * TP + kb + tg];
            af[1] = Qs[(qrow_a + 8) * TP + kb + tg];
            af[2] = Qs[qrow_a * TP + kb + tg + 4];
            af[3] = Qs[(qrow_a + 8) * TP + kb + tg + 4];
#pragma unroll
            for (int j = 0; j < 8; j++) {
                int nc = j * 8 + gq;
                uint b0 = Ks[nc * TP + kb + tg];
                uint b1 = Ks[nc * TP + kb + tg + 4];
                mma_tf32(S[j], af, b0, b1);
            }
        }

        // ---- stage next tile EARLY (loads hide under exp + PV) ----
        if (kc0 + 64 < gcnt) {
            uint* Kn = Ks0 + (buf ^ 1) * 64 * TP;
            uint* Vn = Vt0 + (buf ^ 1) * 64 * TP;
            int kcn = min(64, gcnt - kc0 - 64);
            int krow = goff + kc0 + 64 + min(li, kcn - 1);
            const float* kptr = g_k + (size_t)krow * DMODEL + h * DPH + d0;
            const float* vptr = g_v + (size_t)krow * DMODEL + h * DPH + d0;
#pragma unroll
            for (int f = 0; f < 4; f++) {
                float4 kv = *(const float4*)(kptr + 4 * f);
                uint4 uk = {cvt_tf32(kv.x), cvt_tf32(kv.y), cvt_tf32(kv.z), cvt_tf32(kv.w)};
                *(uint4*)&Kn[li * TP + d0 + 4 * f] = uk;
                float4 vv = *(const float4*)(vptr + 4 * f);
                Vn[(d0 + 4 * f + 0) * TP + li] = cvt_tf32(vv.x);
                Vn[(d0 + 4 * f + 1) * TP + li] = cvt_tf32(vv.y);
                Vn[(d0 + 4 * f + 2) * TP + li] = cvt_tf32(vv.z);
                Vn[(d0 + 4 * f + 3) * TP + li] = cvt_tf32(vv.w);
            }
        }

        // ---- exp (no-max; scores bounded) + mask + warp-private Ps + lsum ----
#pragma unroll
        for (int j = 0; j < 8; j++) {
            int c0 = j * 8 + 2 * tg;
            bool v0 = c0 < kcnt, v1 = c0 + 1 < kcnt;
            float p00 = v0 ? __expf(S[j][0]) : 0.f;
            float p01 = v1 ? __expf(S[j][1]) : 0.f;
            float p10 = v0 ? __expf(S[j][2]) : 0.f;
            float p11 = v1 ? __expf(S[j][3]) : 0.f;
            lsum0 += p00 + p01;
            lsum1 += p10 + p11;
            uint2 ua = {cvt_tf32(p00), cvt_tf32(p01)};
            *(uint2*)&Ps[qrow_a * TP + c0] = ua;
            uint2 ub = {cvt_tf32(p10), cvt_tf32(p11)};
            *(uint2*)&Ps[(qrow_a + 8) * TP + c0] = ub;
        }
        __syncwarp();   // order Ps stores before warp-local PV reads

        // ---- O += P V : warp tile 16q x 64d ----
#pragma unroll
        for (int kb = 0; kb < 64; kb += 8) {
            uint af[4];
            af[0] = Ps[qrow_a * TP + kb + tg];
            af[1] = Ps[(qrow_a + 8) * TP + kb + tg];
            af[2] = Ps[qrow_a * TP + kb + tg + 4];
            af[3] = Ps[(qrow_a + 8) * TP + kb + tg + 4];
#pragma unroll
            for (int j = 0; j < 8; j++) {
                int nc = j * 8 + gq;
                uint b0 = Vt[nc * TP + kb + tg];
                uint b1 = Vt[nc * TP + kb + tg + 4];
                mma_tf32(O[j], af, b0, b1);
            }
        }
        buf ^= 1;
    }

    lsum0 += __shfl_xor_sync(0xffffffffu, lsum0, 1);
    lsum0 += __shfl_xor_sync(0xffffffffu, lsum0, 2);
    lsum1 += __shfl_xor_sync(0xffffffffu, lsum1, 1);
    lsum1 += __shfl_xor_sync(0xffffffffu, lsum1, 2);
    float inv0 = 1.f / lsum0;
    float inv1 = 1.f / lsum1;

#pragma unroll
    for (int j = 0; j < 8; j++) {
        int col = h * DPH + j * 8 + 2 * tg;
        if (qrow_a < rows) {
            float2 o = {O[j][0] * inv0, O[j][1] * inv0};
            *(float2*)&g_ctx[(size_t)(goff + row0 + qrow_a) * DMODEL + col] = o;
        }
        if (qrow_a + 8 < rows) {
            float2 o = {O[j][2] * inv1, O[j][3] * inv1};
            *(float2*)&g_ctx[(size_t)(goff + row0 + qrow_a + 8) * DMODEL + col] = o;
        }
    }
}

// -------- fused output projection + residual + LayerNorm: 16-row tiles (R13) --------
__global__ __launch_bounds__(256) void k_proj_ln(
    const float* __restrict__ x,
    const float* __restrict__ Wf, const float* __restrict__ bf,
    const float* __restrict__ gamma, const float* __restrict__ beta,
    float* __restrict__ out)
{
    int row0 = blockIdx.x * 16;

    extern __shared__ __align__(16) uint dsm[];
    uint* As0 = dsm;
    uint* Bs0 = dsm + 2 * 16 * AP2;
    __shared__ int Ts[16];

    int tid = threadIdx.x;
    if (tid < 16) Ts[tid] = g_perm[row0 + tid];
    __syncthreads();

    int lane = tid & 31, warp = tid >> 5;
    int gq = lane >> 2, tg = lane & 3;

    float acc[4][4];
#pragma unroll
    for (int j = 0; j < 4; j++)
#pragma unroll
        for (int e = 0; e < 4; e++) acc[j][e] = 0.f;

    int am = tid & 15, aseg = (tid >> 4) & 7;
    int bkk = tid >> 5, bn = (tid & 31) * 8;
    const float* Aptr = g_ctx + (size_t)(row0 + am) * DMODEL + aseg * 4;
    const float* Bptr = Wf + (size_t)bkk * DMODEL + bn;

    float4 av, bv[8];
#define PLN_LOAD(s)                                                        \
    {   int kk0 = (s) * 32;                                                \
        if (tid < 128) av = *(const float4*)(Aptr + kk0);                  \
        _Pragma("unroll")                                                  \
        for (int t = 0; t < 4; t++) {                                      \
            bv[2 * t]     = *(const float4*)(Bptr + (size_t)(kk0 + 8 * t) * DMODEL);     \
            bv[2 * t + 1] = *(const float4*)(Bptr + (size_t)(kk0 + 8 * t) * DMODEL + 4); \
        } }
#define PLN_STORE(b_)                                                      \
    {   if (tid < 128) {                                                   \
            uint4 ua = {cvt_tf32(av.x), cvt_tf32(av.y), cvt_tf32(av.z), cvt_tf32(av.w)}; \
            *(uint4*)&As0[(b_) * 16 * AP2 + am * AP2 + aseg * 4] = ua;     \
        }                                                                  \
        _Pragma("unroll")                                                  \
        for (int t = 0; t < 4; t++) {                                      \
            uint4 w0 = {cvt_tf32(bv[2*t].x), cvt_tf32(bv[2*t].y), cvt_tf32(bv[2*t].z), cvt_tf32(bv[2*t].w)}; \
            uint4 w1 = {cvt_tf32(bv[2*t+1].x), cvt_tf32(bv[2*t+1].y), cvt_tf32(bv[2*t+1].z), cvt_tf32(bv[2*t+1].w)}; \
            *(uint4*)&Bs0[(b_) * 32 * BPP + (bkk + 8 * t) * BPP + bn]     = w0; \
            *(uint4*)&Bs0[(b_) * 32 * BPP + (bkk + 8 * t) * BPP + bn + 4] = w1; \
        } }

    PLN_LOAD(0);
    PLN_STORE(0);
    __syncthreads();
#pragma unroll
    for (int s = 0; s < 8; s++) {
        int cur = s & 1;
        if (s < 7) PLN_LOAD(s + 1);
        const uint* As = As0 + cur * 16 * AP2;
        const uint* Bs = Bs0 + cur * 32 * BPP;
#pragma unroll
        for (int kb = 0; kb < 32; kb += 8) {
            uint af[4];
            af[0] = As[gq       * AP2 + kb + tg];
            af[1] = As[(gq + 8) * AP2 + kb + tg];
            af[2] = As[gq       * AP2 + kb + tg + 4];
            af[3] = As[(gq + 8) * AP2 + kb + tg + 4];
#pragma unroll
            for (int j = 0; j < 4; j++) {
                int nc = warp * 32 + j * 8 + gq;
                uint b0 = Bs[(kb + tg)     * BPP + nc];
                uint b1 = Bs[(kb + tg + 4) * BPP + nc];
                mma_tf32(acc[j], af, b0, b1);
            }
        }
        if (s < 7) {
            PLN_STORE(cur ^ 1);
            __syncthreads();
        }
    }

    __syncthreads();
    float* Hs = (float*)dsm;
#pragma unroll
    for (int j = 0; j < 4; j++) {
        int col = warp * 32 + j * 8 + tg * 2;
        float2 b2 = *(const float2*)&bf[col];
        float2 xa = *(const float2*)&x[(size_t)Ts[gq] * DMODEL + col];
        float2 xb = *(const float2*)&x[(size_t)Ts[gq + 8] * DMODEL + col];
        Hs[gq * HP + col]     = acc[j][0] + b2.x + xa.x;
        Hs[gq * HP + col + 1] = acc[j][1] + b2.y + xa.y;
        Hs[(gq + 8) * HP + col]     = acc[j][2] + b2.x + xb.x;
        Hs[(gq + 8) * HP + col + 1] = acc[j][3] + b2.y + xb.y;
    }
    __syncthreads();

#pragma unroll
    for (int i = 0; i < 2; i++) {
        int row = warp * 2 + i;
        float4 v0 = *(const float4*)&Hs[row * HP + lane * 8];
        float4 v1 = *(const float4*)&Hs[row * HP + lane * 8 + 4];
        float s  = (v0.x + v0.y + v0.z + v0.w) + (v1.x + v1.y + v1.z + v1.w);
        float sq = v0.x * v0.x + v0.y * v0.y + v0.z * v0.z + v0.w * v0.w
                 + v1.x * v1.x + v1.y * v1.y + v1.z * v1.z + v1.w * v1.w;
#pragma unroll
        for (int off = 16; off > 0; off >>= 1) {
            s  += __shfl_xor_sync(0xffffffffu, s, off);
            sq += __shfl_xor_sync(0xffffffffu, sq, off);
        }
        float mean = s * (1.f / DMODEL);
        float var  = sq * (1.f / DMODEL) - mean * mean;
        float inv  = rsqrtf(var + LN_EPS);
        int orow = Ts[row];
        float4 g0 = *(const float4*)&gamma[lane * 8];
        float4 g1 = *(const float4*)&gamma[lane * 8 + 4];
        float4 be0 = *(const float4*)&beta[lane * 8];
        float4 be1 = *(const float4*)&beta[lane * 8 + 4];
        float4 o0 = {g0.x * (v0.x - mean) * inv + be0.x,
                     g0.y * (v0.y - mean) * inv + be0.y,
                     g0.z * (v0.z - mean) * inv + be0.z,
                     g0.w * (v0.w - mean) * inv + be0.w};
        float4 o1 = {g1.x * (v1.x - mean) * inv + be1.x,
                     g1.y * (v1.y - mean) * inv + be1.y,
                     g1.z * (v1.z - mean) * inv + be1.z,
                     g1.w * (v1.w - mean) * inv + be1.w};
        *(float4*)&out[(size_t)orow * DMODEL + lane * 8]     = o0;
        *(float4*)&out[(size_t)orow * DMODEL + lane * 8 + 4] = o1;
    }
}

// -------- launch --------
extern "C" void kernel_launch(void* const* d_in, const int* in_sizes, int n_in,
                              void* d_out, int out_size)
{
    const float* x     = (const float*)d_in[0];
    const int*   label = (const int*)  d_in[1];
    const float* Wq    = (const float*)d_in[2];
    const float* bq    = (const float*)d_in[3];
    const float* Wk    = (const float*)d_in[4];
    const float* bk    = (const float*)d_in[5];
    const float* Wv    = (const float*)d_in[6];
    const float* bv    = (const float*)d_in[7];
    const float* Wf    = (const float*)d_in[8];
    const float* bf    = (const float*)d_in[9];
    const float* gamma = (const float*)d_in[10];
    const float* beta  = (const float*)d_in[11];
    float* out = (float*)d_out;

    const int ATTN_SMEM = 8 * 64 * TP * 4;                    // 139264 B
    const int PLN_SMEM  = (2 * 16 * AP2 + 2 * 32 * BPP) * 4;  // 72192 B

    static bool attr_done = false;
    if (!attr_done) {
        cudaFuncSetAttribute(k_attn, cudaFuncAttributeMaxDynamicSharedMemorySize, ATTN_SMEM);
        cudaFuncSetAttribute(k_attn, cudaFuncAttributePreferredSharedMemoryCarveout, 100);
        cudaFuncSetAttribute(k_proj_ln, cudaFuncAttributeMaxDynamicSharedMemorySize, PLN_SMEM);
        cudaFuncSetAttribute(k_proj_ln, cudaFuncAttributePreferredSharedMemoryCarveout, 100);
        attr_done = true;
    }

    k_sort<<<1, 1024>>>(label);
    k_qkv<<<dim3(64, 2, NEXP), 256>>>(x, Wq, bq, Wk, bk, Wv, bv);
    k_attn<<<dim3(32, NEXP, NHEAD), 256, ATTN_SMEM>>>();
    k_proj_ln<<<256, 256, PLN_SMEM>>>(x, Wf, bf, gamma, beta, out);
}